// round 1
// baseline (speedup 1.0000x reference)
#include <cuda_runtime.h>
#include <cuda_bf16.h>
#include <math.h>

#define N_NODES 50000
#define E_EDGES 600000
#define B_GR    128
#define D       128
#define NHEAD   4
#define DH      32
#define NEG_SLOPE 0.2f
#define SCAN_NBLK ((N_NODES + 255) / 256)   // 196

// ---------------- device scratch (no allocs allowed) ----------------
__device__ int   g_is64;
__device__ int   d_src[E_EDGES];
__device__ int   d_dst[E_EDGES];
__device__ int   d_gid[N_NODES];
__device__ int   d_count[N_NODES];
__device__ int   d_rowptr[N_NODES + 1];
__device__ int   d_cur[N_NODES];
__device__ int   d_col[E_EDGES];
__device__ int   d_part[SCAN_NBLK];
__device__ float d_z[N_NODES * D];
__device__ float d_as[N_NODES * NHEAD];
__device__ float d_ad[N_NODES * NHEAD];
__device__ float d_hA[N_NODES * D];
__device__ float d_hB[N_NODES * D];
__device__ float d_z0[D];
__device__ float d_gsum[B_GR * D];
__device__ int   d_gcnt[B_GR];

// ---------------- helpers ----------------
__device__ __forceinline__ float lrelu(float x) { return x >= 0.f ? x : NEG_SLOPE * x; }
__device__ __forceinline__ float eluf(float x)  { return x > 0.f ? x : expm1f(x); }

// ---------------- dtype detection + decode ----------------
__global__ void detect_k(const int* __restrict__ edge32) {
    // int64 little-endian with values < 2^31 -> every odd 32-bit word is 0.
    // int32 data -> odd words are random node ids (nonzero almost surely).
    __shared__ int any_nz;
    if (threadIdx.x == 0) any_nz = 0;
    __syncthreads();
    for (int i = threadIdx.x; i < 1024; i += blockDim.x) {
        if (edge32[2 * i + 1] != 0) atomicOr(&any_nz, 1);
    }
    __syncthreads();
    if (threadIdx.x == 0) g_is64 = any_nz ? 0 : 1;
}

__global__ void decode_edges_k(const void* __restrict__ edge) {
    int e = blockIdx.x * blockDim.x + threadIdx.x;
    if (e >= E_EDGES) return;
    if (g_is64) {
        const long long* p = (const long long*)edge;
        d_src[e] = (int)p[e];
        d_dst[e] = (int)p[E_EDGES + e];
    } else {
        const int* p = (const int*)edge;
        d_src[e] = p[e];
        d_dst[e] = p[E_EDGES + e];
    }
}

__global__ void decode_ptr_k(const void* __restrict__ ptr) {
    int n = blockIdx.x * blockDim.x + threadIdx.x;
    if (n >= N_NODES) return;
    d_gid[n] = g_is64 ? (int)((const long long*)ptr)[n] : ((const int*)ptr)[n];
}

__global__ void zero_k() {
    int i = blockIdx.x * blockDim.x + threadIdx.x;
    if (i < N_NODES) { d_count[i] = 0; d_cur[i] = 0; }
    if (i < B_GR * D) d_gsum[i] = 0.f;
    if (i < B_GR)     d_gcnt[i] = 0;
}

// ---------------- CSR build ----------------
__global__ void hist_k() {
    int e = blockIdx.x * blockDim.x + threadIdx.x;
    if (e < E_EDGES) atomicAdd(&d_count[d_dst[e]], 1);
}

__global__ void scan1_k() {
    __shared__ int sh[256];
    int i = blockIdx.x * 256 + threadIdx.x;
    int v = (i < N_NODES) ? d_count[i] : 0;
    sh[threadIdx.x] = v;
    __syncthreads();
    for (int off = 128; off > 0; off >>= 1) {
        if (threadIdx.x < off) sh[threadIdx.x] += sh[threadIdx.x + off];
        __syncthreads();
    }
    if (threadIdx.x == 0) d_part[blockIdx.x] = sh[0];
}

__global__ void scan2_k() {
    __shared__ int sh[256];
    int t = threadIdx.x;
    int v = (t < SCAN_NBLK) ? d_part[t] : 0;
    sh[t] = v;
    __syncthreads();
    for (int off = 1; off < 256; off <<= 1) {
        int tv = (t >= off) ? sh[t - off] : 0;
        __syncthreads();
        sh[t] += tv;
        __syncthreads();
    }
    if (t < SCAN_NBLK) d_part[t] = sh[t] - v;   // exclusive
    if (t == 0) d_rowptr[N_NODES] = E_EDGES;
}

__global__ void scan3_k() {
    __shared__ int sh[256];
    int i = blockIdx.x * 256 + threadIdx.x;
    int t = threadIdx.x;
    int v = (i < N_NODES) ? d_count[i] : 0;
    sh[t] = v;
    __syncthreads();
    for (int off = 1; off < 256; off <<= 1) {
        int tv = (t >= off) ? sh[t - off] : 0;
        __syncthreads();
        sh[t] += tv;
        __syncthreads();
    }
    if (i < N_NODES) d_rowptr[i] = d_part[blockIdx.x] + sh[t] - v;
}

__global__ void fill_k() {
    int e = blockIdx.x * blockDim.x + threadIdx.x;
    if (e >= E_EDGES) return;
    int d = d_dst[e];
    int pos = atomicAdd(&d_cur[d], 1);
    d_col[d_rowptr[d] + pos] = d_src[e];
}

// ---------------- layer 1 analytic shortcut ----------------
__global__ void z0_k(const float* __restrict__ emb, const float* __restrict__ W0) {
    int c = threadIdx.x;
    float acc = 0.f;
    for (int k = 0; k < D; k++) acc += emb[k] * W0[k * D + c];
    d_z0[c] = acc;
}

__global__ void h1_k(const float* __restrict__ emb) {
    int i = blockIdx.x * blockDim.x + threadIdx.x;   // float4 index
    if (i >= N_NODES * 32) return;
    int n = i >> 5, q = i & 31;
    float m = (float)(d_count[n] + 2);               // 1 + deg_total, deg_total = count+1
    float4 z = ((const float4*)d_z0)[q];
    float4 e = ((const float4*)emb)[q];
    float4 o;
    o.x = eluf(m * z.x) + e.x;
    o.y = eluf(m * z.y) + e.y;
    o.z = eluf(m * z.z) + e.z;
    o.w = eluf(m * z.w) + e.w;
    ((float4*)d_hA)[i] = o;
}

// ---------------- GEMM: z = h @ W  (N x 128) @ (128 x 128) ----------------
__global__ void gemm_k(const float* __restrict__ W, int sel) {
    const float* __restrict__ hin = sel ? d_hB : d_hA;
    __shared__ float Ws[32][128];
    __shared__ float Hs[64][33];
    int tid = threadIdx.x;
    int tx = tid & 15, ty = tid >> 4;
    int row0 = blockIdx.x * 64;
    float acc[4][8];
#pragma unroll
    for (int i = 0; i < 4; i++)
#pragma unroll
        for (int j = 0; j < 8; j++) acc[i][j] = 0.f;

    for (int k0 = 0; k0 < 128; k0 += 32) {
#pragma unroll
        for (int i = 0; i < 4; i++) {
            int idx = tid + i * 256;         // 1024 float4 units
            int kk = idx >> 5, c4 = idx & 31;
            ((float4*)Ws[kk])[c4] = ((const float4*)W)[(k0 + kk) * 32 + c4];
        }
#pragma unroll
        for (int i = 0; i < 2; i++) {
            int idx = tid + i * 256;         // 512 float4 units
            int r = idx >> 3, k4 = idx & 7;
            int row = row0 + r;
            float4 v = make_float4(0.f, 0.f, 0.f, 0.f);
            if (row < N_NODES) v = ((const float4*)hin)[row * 32 + (k0 >> 2) + k4];
            Hs[r][k4 * 4 + 0] = v.x; Hs[r][k4 * 4 + 1] = v.y;
            Hs[r][k4 * 4 + 2] = v.z; Hs[r][k4 * 4 + 3] = v.w;
        }
        __syncthreads();
#pragma unroll
        for (int kk = 0; kk < 32; kk++) {
            float a[4];
#pragma unroll
            for (int i = 0; i < 4; i++) a[i] = Hs[ty * 4 + i][kk];
            float4 b0 = ((float4*)Ws[kk])[tx * 2];
            float4 b1 = ((float4*)Ws[kk])[tx * 2 + 1];
            float bb[8] = {b0.x, b0.y, b0.z, b0.w, b1.x, b1.y, b1.z, b1.w};
#pragma unroll
            for (int i = 0; i < 4; i++)
#pragma unroll
                for (int j = 0; j < 8; j++) acc[i][j] = fmaf(a[i], bb[j], acc[i][j]);
        }
        __syncthreads();
    }
#pragma unroll
    for (int i = 0; i < 4; i++) {
        int row = row0 + ty * 4 + i;
        if (row < N_NODES) {
            float4 o0 = make_float4(acc[i][0], acc[i][1], acc[i][2], acc[i][3]);
            float4 o1 = make_float4(acc[i][4], acc[i][5], acc[i][6], acc[i][7]);
            ((float4*)d_z)[row * 32 + tx * 2] = o0;
            ((float4*)d_z)[row * 32 + tx * 2 + 1] = o1;
        }
    }
}

// ---------------- attention logits a_s, a_d ----------------
__global__ void att_k(const float* __restrict__ att_s, const float* __restrict__ att_d) {
    int warp = (blockIdx.x * blockDim.x + threadIdx.x) >> 5;
    if (warp >= N_NODES) return;
    int lane = threadIdx.x & 31;
    int head = lane >> 3;
    float4 z = ((const float4*)d_z)[warp * 32 + lane];
    float4 s = ((const float4*)att_s)[head * 8 + (lane & 7)];
    float4 t = ((const float4*)att_d)[head * 8 + (lane & 7)];
    float ps = z.x * s.x + z.y * s.y + z.z * s.z + z.w * s.w;
    float pd = z.x * t.x + z.y * t.y + z.z * t.z + z.w * t.w;
#pragma unroll
    for (int o = 4; o >= 1; o >>= 1) {
        ps += __shfl_xor_sync(0xffffffffu, ps, o);
        pd += __shfl_xor_sync(0xffffffffu, pd, o);
    }
    if ((lane & 7) == 0) {
        d_as[warp * 4 + head] = ps;
        d_ad[warp * 4 + head] = pd;
    }
}

// ---------------- fused softmax + aggregation + elu + residual ----------------
__global__ void agg_k(int sel) {
    const float* __restrict__ hin = sel ? d_hB : d_hA;
    float* __restrict__ hout = sel ? d_hA : d_hB;
    int n = (blockIdx.x * blockDim.x + threadIdx.x) >> 5;
    if (n >= N_NODES) return;
    int lane = threadIdx.x & 31;
    int head = lane >> 3;

    float ad = d_ad[n * 4 + head];
    float as_self = d_as[n * 4 + head];
    int beg = d_rowptr[n], end = d_rowptr[n + 1];

    // pass 1: segment max (per head, every lane walks all edges of its node)
    float amax = lrelu(as_self + ad);
    for (int e = beg; e < end; e++) {
        int s = d_col[e];
        amax = fmaxf(amax, lrelu(d_as[s * 4 + head] + ad));
    }

    // pass 2: den, S0 = sum z, S1 = sum z*ex   ->  out = S1/den + S0
    float ex = expf(lrelu(as_self + ad) - amax);
    float den = ex;
    float4 zv = ((const float4*)d_z)[n * 32 + lane];
    float4 S0 = zv;
    float4 S1 = make_float4(zv.x * ex, zv.y * ex, zv.z * ex, zv.w * ex);
    for (int e = beg; e < end; e++) {
        int s = d_col[e];
        float exx = expf(lrelu(d_as[s * 4 + head] + ad) - amax);
        den += exx;
        float4 z2 = ((const float4*)d_z)[s * 32 + lane];
        S0.x += z2.x; S0.y += z2.y; S0.z += z2.z; S0.w += z2.w;
        S1.x = fmaf(z2.x, exx, S1.x); S1.y = fmaf(z2.y, exx, S1.y);
        S1.z = fmaf(z2.z, exx, S1.z); S1.w = fmaf(z2.w, exx, S1.w);
    }
    float inv = 1.f / den;
    float4 r = ((const float4*)hin)[n * 32 + lane];
    float4 o;
    o.x = eluf(fmaf(S1.x, inv, S0.x)) + r.x;
    o.y = eluf(fmaf(S1.y, inv, S0.y)) + r.y;
    o.z = eluf(fmaf(S1.z, inv, S0.z)) + r.z;
    o.w = eluf(fmaf(S1.w, inv, S0.w)) + r.w;
    ((float4*)hout)[n * 32 + lane] = o;
}

// ---------------- graph readout: run-length batched segment sum ----------------
__global__ void readout_k() {
    int warp = (blockIdx.x * blockDim.x + threadIdx.x) >> 5;
    int lane = threadIdx.x & 31;
    int n0 = warp * 64;
    if (n0 >= N_NODES) return;
    int n1 = min(n0 + 64, N_NODES);
    int gcur = d_gid[n0];
    float4 acc = make_float4(0.f, 0.f, 0.f, 0.f);
    int run = 0;
    for (int n = n0; n < n1; n++) {
        int g = d_gid[n];
        if (g != gcur) {
            atomicAdd(&d_gsum[gcur * D + lane * 4 + 0], acc.x);
            atomicAdd(&d_gsum[gcur * D + lane * 4 + 1], acc.y);
            atomicAdd(&d_gsum[gcur * D + lane * 4 + 2], acc.z);
            atomicAdd(&d_gsum[gcur * D + lane * 4 + 3], acc.w);
            if (lane == 0) atomicAdd(&d_gcnt[gcur], run);
            acc = make_float4(0.f, 0.f, 0.f, 0.f);
            run = 0; gcur = g;
        }
        float4 v = ((const float4*)d_hA)[n * 32 + lane];
        acc.x += v.x; acc.y += v.y; acc.z += v.z; acc.w += v.w;
        run++;
    }
    atomicAdd(&d_gsum[gcur * D + lane * 4 + 0], acc.x);
    atomicAdd(&d_gsum[gcur * D + lane * 4 + 1], acc.y);
    atomicAdd(&d_gsum[gcur * D + lane * 4 + 2], acc.z);
    atomicAdd(&d_gsum[gcur * D + lane * 4 + 3], acc.w);
    if (lane == 0) atomicAdd(&d_gcnt[gcur], run);
}

// ---------------- MLP readout ----------------
__global__ void mlp_k(const float* __restrict__ w0, const float* __restrict__ b0,
                      const float* __restrict__ w1, const float* __restrict__ b1,
                      float* __restrict__ y) {
    int b = blockIdx.x;
    int j = threadIdx.x;            // 64 hidden units
    float inv = 1.f / fmaxf((float)d_gcnt[b], 1.f);
    float acc = b0[j];
    for (int k = 0; k < D; k++) {
        float g = fmaxf(d_gsum[b * D + k] * inv, 0.f);
        acc = fmaf(g, w0[k * 64 + j], acc);
    }
    float t = fmaxf(acc, 0.f) * w1[j];
    __shared__ float sh[64];
    sh[j] = t;
    __syncthreads();
    for (int off = 32; off > 0; off >>= 1) {
        if (j < off) sh[j] += sh[j + off];
        __syncthreads();
    }
    if (j == 0) y[b] = sh[0] + b1[0];
}

// ---------------- launcher ----------------
extern "C" void kernel_launch(void* const* d_in, const int* in_sizes, int n_in,
                              void* d_out, int out_size) {
    const void*  edge  = d_in[1];
    const void*  ptr   = d_in[2];
    const float* emb   = (const float*)d_in[3];
    const float* lin_w = (const float*)d_in[4];
    const float* att_s = (const float*)d_in[5];
    const float* att_d = (const float*)d_in[6];
    const float* w0    = (const float*)d_in[7];
    const float* b0    = (const float*)d_in[8];
    const float* w1    = (const float*)d_in[9];
    const float* b1    = (const float*)d_in[10];
    float* y = (float*)d_out;

    const int EB = (E_EDGES + 255) / 256;       // 2344
    const int NB = SCAN_NBLK;                   // 196
    const int WB = (N_NODES * 32 + 255) / 256;  // 6250 (float4 threads / warp-per-node)

    detect_k<<<1, 256>>>((const int*)edge);
    zero_k<<<NB, 256>>>();
    decode_edges_k<<<EB, 256>>>(edge);
    decode_ptr_k<<<NB, 256>>>(ptr);
    hist_k<<<EB, 256>>>();
    scan1_k<<<NB, 256>>>();
    scan2_k<<<1, 256>>>();
    scan3_k<<<NB, 256>>>();
    fill_k<<<EB, 256>>>();

    // layer 1 (analytic: identical input rows)
    z0_k<<<1, 128>>>(emb, lin_w);
    h1_k<<<WB, 256>>>(emb);

    // layers 2 and 3 (full)
    for (int l = 1; l < 3; l++) {
        int sel = l - 1;   // 0: hA->hB, 1: hB->hA
        gemm_k<<<(N_NODES + 63) / 64, 256>>>(lin_w + l * D * D, sel);
        att_k<<<WB, 256>>>(att_s + l * NHEAD * DH, att_d + l * NHEAD * DH);
        agg_k<<<WB, 256>>>(sel);
    }

    readout_k<<<((N_NODES + 63) / 64 * 32 + 255) / 256, 256>>>();
    mlp_k<<<B_GR, 64>>>(w0, b0, w1, b1, y);
}

// round 2
// speedup vs baseline: 1.1603x; 1.1603x over previous
#include <cuda_runtime.h>
#include <cuda_bf16.h>
#include <math.h>

typedef unsigned long long ull;

#define N_NODES 50000
#define E_EDGES 600000
#define B_GR    128
#define D       128
#define NHEAD   4
#define DH      32
#define NEG_SLOPE 0.2f
#define SCAN_NBLK ((N_NODES + 255) / 256)   // 196
#define EB ((E_EDGES + 255) / 256)          // 2344
#define WB ((N_NODES * 32 + 255) / 256)     // 6250

// ---------------- device scratch ----------------
__device__ int   g_is64;
__device__ int   d_src[E_EDGES];
__device__ int   d_dst[E_EDGES];
__device__ int   d_gid[N_NODES];
__device__ int   d_count[N_NODES];
__device__ int   d_rowptr[N_NODES + 1];
__device__ int   d_cur[N_NODES];
__device__ int   d_col[E_EDGES];
__device__ int   d_part[SCAN_NBLK];
__device__ float d_z[N_NODES * D];
__device__ float d_as[N_NODES * NHEAD];
__device__ float d_ad[N_NODES * NHEAD];
__device__ float d_hA[N_NODES * D];
__device__ float d_hB[N_NODES * D];
__device__ float d_z0[D];
__device__ float d_gsum[B_GR * D];
__device__ int   d_gcnt[B_GR];

// ---------------- helpers ----------------
__device__ __forceinline__ float lrelu(float x) { return x >= 0.f ? x : NEG_SLOPE * x; }
__device__ __forceinline__ float eluf(float x)  { return x > 0.f ? x : expm1f(x); }
__device__ __forceinline__ void ffma2(ull &d, ull a, ull b) {
    asm("fma.rn.f32x2 %0, %1, %2, %0;" : "+l"(d) : "l"(a), "l"(b));
}
__device__ __forceinline__ ull dup2(float v) {
    ull r;
    asm("mov.b64 %0, {%1, %1};" : "=l"(r) : "f"(v));
    return r;
}

// ---------------- prep: zero scratch + dtype detect + z0 ----------------
__global__ void prep_k(const int* __restrict__ edge32,
                       const float* __restrict__ emb, const float* __restrict__ W0) {
    int i = blockIdx.x * 256 + threadIdx.x;
    if (i < N_NODES) { d_count[i] = 0; d_cur[i] = 0; }
    if (i < B_GR * D) d_gsum[i] = 0.f;
    if (i < B_GR)     d_gcnt[i] = 0;

    if (blockIdx.x == 0) {
        // int64 LE with values < 2^31 -> every odd 32-bit word is 0.
        __shared__ int any_nz;
        if (threadIdx.x == 0) any_nz = 0;
        __syncthreads();
        int nz = 0;
        for (int t = threadIdx.x; t < 1024; t += 256)
            if (edge32[2 * t + 1] != 0) nz = 1;
        if (nz) atomicOr(&any_nz, 1);
        __syncthreads();
        if (threadIdx.x == 0) g_is64 = any_nz ? 0 : 1;
    }
    if (blockIdx.x == 1 && threadIdx.x < D) {
        int c = threadIdx.x;
        float acc = 0.f;
        for (int k = 0; k < D; k++) acc += emb[k] * W0[k * D + c];
        d_z0[c] = acc;
    }
}

// ---------------- decode edges+ptr, fused in-degree histogram ----------------
__global__ void decode_k(const void* __restrict__ edge, const void* __restrict__ ptr) {
    int b = blockIdx.x;
    if (b < EB) {
        int e = b * 256 + threadIdx.x;
        if (e >= E_EDGES) return;
        int s, d;
        if (g_is64) {
            const long long* p = (const long long*)edge;
            s = (int)p[e]; d = (int)p[E_EDGES + e];
        } else {
            const int* p = (const int*)edge;
            s = p[e]; d = p[E_EDGES + e];
        }
        d_src[e] = s; d_dst[e] = d;
        atomicAdd(&d_count[d], 1);
    } else {
        int n = (b - EB) * 256 + threadIdx.x;
        if (n >= N_NODES) return;
        d_gid[n] = g_is64 ? (int)((const long long*)ptr)[n] : ((const int*)ptr)[n];
    }
}

// ---------------- CSR build: scans ----------------
__global__ void scan1_k() {
    __shared__ int sh[256];
    int i = blockIdx.x * 256 + threadIdx.x;
    int v = (i < N_NODES) ? d_count[i] : 0;
    sh[threadIdx.x] = v;
    __syncthreads();
    for (int off = 128; off > 0; off >>= 1) {
        if (threadIdx.x < off) sh[threadIdx.x] += sh[threadIdx.x + off];
        __syncthreads();
    }
    if (threadIdx.x == 0) d_part[blockIdx.x] = sh[0];
}

__global__ void scan2_k() {
    __shared__ int sh[256];
    int t = threadIdx.x;
    int v = (t < SCAN_NBLK) ? d_part[t] : 0;
    sh[t] = v;
    __syncthreads();
    for (int off = 1; off < 256; off <<= 1) {
        int tv = (t >= off) ? sh[t - off] : 0;
        __syncthreads();
        sh[t] += tv;
        __syncthreads();
    }
    if (t < SCAN_NBLK) d_part[t] = sh[t] - v;   // exclusive
    if (t == 0) d_rowptr[N_NODES] = E_EDGES;
}

__global__ void scan3_k() {
    __shared__ int sh[256];
    int i = blockIdx.x * 256 + threadIdx.x;
    int t = threadIdx.x;
    int v = (i < N_NODES) ? d_count[i] : 0;
    sh[t] = v;
    __syncthreads();
    for (int off = 1; off < 256; off <<= 1) {
        int tv = (t >= off) ? sh[t - off] : 0;
        __syncthreads();
        sh[t] += tv;
        __syncthreads();
    }
    if (i < N_NODES) d_rowptr[i] = d_part[blockIdx.x] + sh[t] - v;
}

// ---------------- CSR fill + layer-1 analytic shortcut (fused) ----------------
__global__ void fill_h1_k(const float* __restrict__ emb) {
    int b = blockIdx.x;
    if (b < EB) {
        int e = b * 256 + threadIdx.x;
        if (e >= E_EDGES) return;
        int d = d_dst[e];
        int pos = atomicAdd(&d_cur[d], 1);
        d_col[d_rowptr[d] + pos] = d_src[e];
    } else {
        int i = (b - EB) * 256 + threadIdx.x;   // float4 index
        if (i >= N_NODES * 32) return;
        int n = i >> 5, q = i & 31;
        float m = (float)(d_count[n] + 2);      // 1 + deg_total
        float4 z = ((const float4*)d_z0)[q];
        float4 e4 = ((const float4*)emb)[q];
        float4 o;
        o.x = eluf(m * z.x) + e4.x;
        o.y = eluf(m * z.y) + e4.y;
        o.z = eluf(m * z.z) + e4.z;
        o.w = eluf(m * z.w) + e4.w;
        ((float4*)d_hA)[i] = o;
    }
}

// ---------------- GEMM: z = h @ W via packed fma.rn.f32x2 ----------------
// Block: 128 rows x 128 cols, 256 threads (ty 0..15 -> 8 rows each; tx 0..15
// -> 4 col-pairs c = 2*tx + 32*j). A duplicated {h,h} in shared (k-major,
// broadcast reads); B read as natural packed pairs (contiguous across tx).
__global__ __launch_bounds__(256) void gemm_k(const float* __restrict__ W, int sel) {
    const float* __restrict__ hin = sel ? d_hB : d_hA;
    __shared__ float Ws[32 * 128];
    __shared__ ull   Hs2[32 * 129];
    int tid = threadIdx.x;
    int tx = tid & 15, ty = tid >> 4;
    int row0 = blockIdx.x * 128;

    ull acc[8][4];
#pragma unroll
    for (int i = 0; i < 8; i++)
#pragma unroll
        for (int j = 0; j < 4; j++) acc[i][j] = 0ull;

    for (int k0 = 0; k0 < 128; k0 += 32) {
        if (k0) __syncthreads();
        // load W chunk: 32 k x 128 cols
#pragma unroll
        for (int i = 0; i < 4; i++) {
            int idx = tid + i * 256;           // 1024 float4
            int kk = idx >> 5, c4 = idx & 31;
            ((float4*)Ws)[kk * 32 + c4] = ((const float4*)W)[(k0 + kk) * 32 + c4];
        }
        // load H chunk duplicated: Hs2[k*129 + r] = {h,h}
#pragma unroll
        for (int i = 0; i < 4; i++) {
            int idx = tid + i * 256;           // 1024 float4
            int r = idx >> 3, k4 = idx & 7;
            int row = row0 + r;
            float4 v = make_float4(0.f, 0.f, 0.f, 0.f);
            if (row < N_NODES) v = ((const float4*)hin)[row * 32 + (k0 >> 2) + k4];
            Hs2[(k4 * 4 + 0) * 129 + r] = dup2(v.x);
            Hs2[(k4 * 4 + 1) * 129 + r] = dup2(v.y);
            Hs2[(k4 * 4 + 2) * 129 + r] = dup2(v.z);
            Hs2[(k4 * 4 + 3) * 129 + r] = dup2(v.w);
        }
        __syncthreads();
#pragma unroll 8
        for (int kk = 0; kk < 32; kk++) {
            ull bb[4];
            const ull* wrow = (const ull*)(Ws + kk * 128);
#pragma unroll
            for (int j = 0; j < 4; j++) bb[j] = wrow[tx + 16 * j];
#pragma unroll
            for (int i = 0; i < 8; i++) {
                ull a = Hs2[kk * 129 + ty * 8 + i];
#pragma unroll
                for (int j = 0; j < 4; j++) ffma2(acc[i][j], a, bb[j]);
            }
        }
    }
#pragma unroll
    for (int i = 0; i < 8; i++) {
        int row = row0 + ty * 8 + i;
        if (row < N_NODES) {
            ull* zrow = (ull*)(d_z + row * D);
#pragma unroll
            for (int j = 0; j < 4; j++) zrow[tx + 16 * j] = acc[i][j];
        }
    }
}

// ---------------- attention logits a_s, a_d ----------------
__global__ void att_k(const float* __restrict__ att_s, const float* __restrict__ att_d) {
    int warp = (blockIdx.x * blockDim.x + threadIdx.x) >> 5;
    if (warp >= N_NODES) return;
    int lane = threadIdx.x & 31;
    int head = lane >> 3;
    float4 z = ((const float4*)d_z)[warp * 32 + lane];
    float4 s = ((const float4*)att_s)[head * 8 + (lane & 7)];
    float4 t = ((const float4*)att_d)[head * 8 + (lane & 7)];
    float ps = z.x * s.x + z.y * s.y + z.z * s.z + z.w * s.w;
    float pd = z.x * t.x + z.y * t.y + z.z * t.z + z.w * t.w;
#pragma unroll
    for (int o = 4; o >= 1; o >>= 1) {
        ps += __shfl_xor_sync(0xffffffffu, ps, o);
        pd += __shfl_xor_sync(0xffffffffu, pd, o);
    }
    if ((lane & 7) == 0) {
        d_as[warp * 4 + head] = ps;
        d_ad[warp * 4 + head] = pd;
    }
}

// ---------------- fused softmax + aggregation + elu + residual ----------------
__global__ void agg_k(int sel) {
    const float* __restrict__ hin = sel ? d_hB : d_hA;
    float* __restrict__ hout = sel ? d_hA : d_hB;
    int n = (blockIdx.x * blockDim.x + threadIdx.x) >> 5;
    if (n >= N_NODES) return;
    int lane = threadIdx.x & 31;
    int head = lane >> 3;

    float ad = d_ad[n * 4 + head];
    float as_self = d_as[n * 4 + head];
    int beg = d_rowptr[n], end = d_rowptr[n + 1];

    // pass 1: segment max
    float amax = lrelu(as_self + ad);
    for (int e = beg; e < end; e++) {
        int s = d_col[e];
        amax = fmaxf(amax, lrelu(d_as[s * 4 + head] + ad));
    }

    // pass 2: den, S0 = sum z, S1 = sum z*ex  ->  out = S1/den + S0
    float ex = __expf(lrelu(as_self + ad) - amax);
    float den = ex;
    float4 zv = ((const float4*)d_z)[n * 32 + lane];
    float4 S0 = zv;
    float4 S1 = make_float4(zv.x * ex, zv.y * ex, zv.z * ex, zv.w * ex);
    for (int e = beg; e < end; e++) {
        int s = d_col[e];
        float exx = __expf(lrelu(d_as[s * 4 + head] + ad) - amax);
        den += exx;
        float4 z2 = ((const float4*)d_z)[s * 32 + lane];
        S0.x += z2.x; S0.y += z2.y; S0.z += z2.z; S0.w += z2.w;
        S1.x = fmaf(z2.x, exx, S1.x); S1.y = fmaf(z2.y, exx, S1.y);
        S1.z = fmaf(z2.z, exx, S1.z); S1.w = fmaf(z2.w, exx, S1.w);
    }
    float inv = 1.f / den;
    float4 r = ((const float4*)hin)[n * 32 + lane];
    float4 o;
    o.x = eluf(fmaf(S1.x, inv, S0.x)) + r.x;
    o.y = eluf(fmaf(S1.y, inv, S0.y)) + r.y;
    o.z = eluf(fmaf(S1.z, inv, S0.z)) + r.z;
    o.w = eluf(fmaf(S1.w, inv, S0.w)) + r.w;
    ((float4*)hout)[n * 32 + lane] = o;
}

// ---------------- graph readout ----------------
__global__ void readout_k() {
    int warp = (blockIdx.x * blockDim.x + threadIdx.x) >> 5;
    int lane = threadIdx.x & 31;
    int n0 = warp * 64;
    if (n0 >= N_NODES) return;
    int n1 = min(n0 + 64, N_NODES);
    int gcur = d_gid[n0];
    float4 acc = make_float4(0.f, 0.f, 0.f, 0.f);
    int run = 0;
    for (int n = n0; n < n1; n++) {
        int g = d_gid[n];
        if (g != gcur) {
            atomicAdd(&d_gsum[gcur * D + lane * 4 + 0], acc.x);
            atomicAdd(&d_gsum[gcur * D + lane * 4 + 1], acc.y);
            atomicAdd(&d_gsum[gcur * D + lane * 4 + 2], acc.z);
            atomicAdd(&d_gsum[gcur * D + lane * 4 + 3], acc.w);
            if (lane == 0) atomicAdd(&d_gcnt[gcur], run);
            acc = make_float4(0.f, 0.f, 0.f, 0.f);
            run = 0; gcur = g;
        }
        float4 v = ((const float4*)d_hA)[n * 32 + lane];
        acc.x += v.x; acc.y += v.y; acc.z += v.z; acc.w += v.w;
        run++;
    }
    atomicAdd(&d_gsum[gcur * D + lane * 4 + 0], acc.x);
    atomicAdd(&d_gsum[gcur * D + lane * 4 + 1], acc.y);
    atomicAdd(&d_gsum[gcur * D + lane * 4 + 2], acc.z);
    atomicAdd(&d_gsum[gcur * D + lane * 4 + 3], acc.w);
    if (lane == 0) atomicAdd(&d_gcnt[gcur], run);
}

// ---------------- MLP readout ----------------
__global__ void mlp_k(const float* __restrict__ w0, const float* __restrict__ b0,
                      const float* __restrict__ w1, const float* __restrict__ b1,
                      float* __restrict__ y) {
    int b = blockIdx.x;
    int j = threadIdx.x;            // 64 hidden units
    float inv = 1.f / fmaxf((float)d_gcnt[b], 1.f);
    float acc = b0[j];
    for (int k = 0; k < D; k++) {
        float g = fmaxf(d_gsum[b * D + k] * inv, 0.f);
        acc = fmaf(g, w0[k * 64 + j], acc);
    }
    float t = fmaxf(acc, 0.f) * w1[j];
    __shared__ float sh[64];
    sh[j] = t;
    __syncthreads();
    for (int off = 32; off > 0; off >>= 1) {
        if (j < off) sh[j] += sh[j + off];
        __syncthreads();
    }
    if (j == 0) y[b] = sh[0] + b1[0];
}

// ---------------- launcher ----------------
extern "C" void kernel_launch(void* const* d_in, const int* in_sizes, int n_in,
                              void* d_out, int out_size) {
    const void*  edge  = d_in[1];
    const void*  ptr   = d_in[2];
    const float* emb   = (const float*)d_in[3];
    const float* lin_w = (const float*)d_in[4];
    const float* att_s = (const float*)d_in[5];
    const float* att_d = (const float*)d_in[6];
    const float* w0    = (const float*)d_in[7];
    const float* b0    = (const float*)d_in[8];
    const float* w1    = (const float*)d_in[9];
    const float* b1    = (const float*)d_in[10];
    float* y = (float*)d_out;

    const int NB = SCAN_NBLK;

    prep_k<<<NB, 256>>>((const int*)edge, emb, lin_w);
    decode_k<<<EB + NB, 256>>>(edge, ptr);
    scan1_k<<<NB, 256>>>();
    scan2_k<<<1, 256>>>();
    scan3_k<<<NB, 256>>>();
    fill_h1_k<<<EB + WB, 256>>>(emb);

    for (int l = 1; l < 3; l++) {
        int sel = l - 1;   // 0: hA->hB, 1: hB->hA
        gemm_k<<<(N_NODES + 127) / 128, 256>>>(lin_w + l * D * D, sel);
        att_k<<<WB, 256>>>(att_s + l * NHEAD * DH, att_d + l * NHEAD * DH);
        agg_k<<<WB, 256>>>(sel);
    }

    readout_k<<<((N_NODES + 63) / 64 * 32 + 255) / 256, 256>>>();
    mlp_k<<<B_GR, 64>>>(w0, b0, w1, b1, y);
}